// round 13
// baseline (speedup 1.0000x reference)
#include <cuda_runtime.h>
#include <cuda_fp16.h>
#include <cstdint>

#define C_   8
#define N_   1024
#define T_   3
#define INF_ 64
#define H_   4
#define F_   64
#define K_   256      // H*F
#define S_   192      // T*F
#define E_   65536
#define CN_  8192

// ---------------- scratch ----------------
__device__ __align__(16) float  g_msrc[CN_];
__device__ __align__(16) float  g_mdst[CN_];
__device__ __align__(16) float  g_asrc[C_*N_*H_];
__device__ __align__(16) float  g_adst[C_*N_*H_];
__device__ __align__(16) float  g_wsrc[T_*3*H_*64];        // [t][b][h][i]
__device__ __align__(16) float  g_wdst[T_*3*H_*64];
__device__ __align__(16) __half g_fch[T_*INF_*K_];         // fc in fp16
__device__ __align__(16) __half g_Fd[(size_t)C_*H_*N_*S_]; // [c*4+h][u][s]
__device__ __align__(16) __half g_At[(size_t)C_*H_*N_*N_]; // [c*4+h][v][u]

// ---------------- helpers ----------------
__device__ __forceinline__ float clipf(float x) {
    return fminf(fmaxf(x, -1e9f), 1e9f);
}
__device__ __forceinline__ float fexp(float x) {
    float y  = x * 1.4426950408889634f;
    int   ni = __float2int_rn(y);
    float f  = y - (float)ni;
    float p  = 1.5403530393381608e-4f;
    p = fmaf(p, f, 1.3333558146428443e-3f);
    p = fmaf(p, f, 9.6181291076284770e-3f);
    p = fmaf(p, f, 5.5504108664821580e-2f);
    p = fmaf(p, f, 2.4022650695910071e-1f);
    p = fmaf(p, f, 6.9314718055994531e-1f);
    p = fmaf(p, f, 1.0f);
    return __int_as_float((ni + 127) << 23) * p;
}
__device__ __forceinline__ uint32_t smem_u32(const void* p) {
    return (uint32_t)__cvta_generic_to_shared(p);
}

// ---------------- K_prep: zero masks + fc->fp16 + compute w (outs no longer zeroed) ----------------
__global__ __launch_bounds__(256) void k_prep(const float* __restrict__ fc,
                                              const float* __restrict__ asv,
                                              const float* __restrict__ adv) {
    int blk = blockIdx.x;
    int tid = threadIdx.x;
    if (blk < 32) {
        int i = blk * 256 + tid;
        g_msrc[i] = 0.f; g_mdst[i] = 0.f;
        return;
    }
    if (blk < 224) {                        // fc fp32 -> fp16 (49152 elements)
        int i = (blk - 32) * 256 + tid;
        g_fch[i] = __float2half(fc[i]);
        return;
    }
    int w = blk - 224;                      // 9 blocks: w[t][b]
    int t = w / 3, b = w - t * 3;
    __shared__ float s_a[256], s_d[256];
    {
        int hh = tid >> 6, ff = tid & 63;
        s_a[tid] = asv[hh * S_ + b * 64 + ff];
        s_d[tid] = adv[hh * S_ + b * 64 + ff];
    }
    __syncthreads();
    int h = tid >> 6, i = tid & 63;
    const float4* fp = reinterpret_cast<const float4*>(
        fc + ((size_t)t * INF_ + i) * K_ + h * 64);
    float4 v[16];
    #pragma unroll
    for (int j = 0; j < 16; ++j) v[j] = fp[j];
    float ws = 0.f, wd = 0.f;
    #pragma unroll
    for (int j = 0; j < 16; ++j) {
        const float* sa = s_a + h * 64 + j * 4;
        const float* sd = s_d + h * 64 + j * 4;
        ws = fmaf(v[j].x, sa[0], ws); wd = fmaf(v[j].x, sd[0], wd);
        ws = fmaf(v[j].y, sa[1], ws); wd = fmaf(v[j].y, sd[1], wd);
        ws = fmaf(v[j].z, sa[2], ws); wd = fmaf(v[j].z, sd[2], wd);
        ws = fmaf(v[j].w, sa[3], ws); wd = fmaf(v[j].w, sd[3], wd);
    }
    int o = ((t * 3 + b) * 4 + h) * 64 + i;
    g_wsrc[o] = ws;
    g_wdst[o] = wd;
}

// ---------------- K1: scatter edge masks (int32) ----------------
__global__ __launch_bounds__(256) void k_scatter(const int* __restrict__ edge) {
    int i = blockIdx.x * 256 + threadIdx.x;
    if (i < E_) {
        g_msrc[edge[i]      & (CN_ - 1)] = 1.f;
        g_mdst[edge[E_ + i] & (CN_ - 1)] = 1.f;
    }
}

// ---------------- Kav: a_src/a_dst (exact fp32) ----------------
__global__ __launch_bounds__(256) void k_av(const float* __restrict__ nf) {
    int W    = blockIdx.x * 8 + (threadIdx.x >> 5);
    int lane = threadIdx.x & 31;
    int c = W >> 10, u = W & 1023;

    float as[4] = {0.f, 0.f, 0.f, 0.f};
    float ad[4] = {0.f, 0.f, 0.f, 0.f};
    #pragma unroll
    for (int b = 0; b < 3; ++b) {
        int q = 3 * u + b, t = q >> 10, n = q & 1023;
        const float* row = nf + ((size_t)(c * N_ + n) * T_ + t) * INF_;
        float x0 = row[lane], x1 = row[lane + 32];
        const float* ws = g_wsrc + ((t * 3 + b) * 4) * 64;
        const float* wd = g_wdst + ((t * 3 + b) * 4) * 64;
        #pragma unroll
        for (int h = 0; h < 4; ++h) {
            as[h] = fmaf(x0, ws[h * 64 + lane], as[h]);
            as[h] = fmaf(x1, ws[h * 64 + lane + 32], as[h]);
            ad[h] = fmaf(x0, wd[h * 64 + lane], ad[h]);
            ad[h] = fmaf(x1, wd[h * 64 + lane + 32], ad[h]);
        }
    }
    #pragma unroll
    for (int o = 16; o; o >>= 1) {
        #pragma unroll
        for (int h = 0; h < 4; ++h) {
            as[h] += __shfl_xor_sync(0xffffffffu, as[h], o);
            ad[h] += __shfl_xor_sync(0xffffffffu, ad[h], o);
        }
    }
    if (lane == 0) {
        int base = (c * N_ + u) * H_;
        *reinterpret_cast<float4*>(&g_asrc[base]) = make_float4(as[0], as[1], as[2], as[3]);
        *reinterpret_cast<float4*>(&g_adst[base]) = make_float4(ad[0], ad[1], ad[2], ad[3]);
    }
}

// ---------------- K2: feat GEMM tensor cores, M=64 tiles, B from g_fch ----------------
#define LDA2 72
#define LDB2 264
__global__ __launch_bounds__(256) void k_feat_tc(const float* __restrict__ nf) {
    __shared__ __align__(16) __half As[64 * LDA2];
    __shared__ __align__(16) __half Bs[64 * LDB2];

    int n0 = blockIdx.x * 64;
    int t  = blockIdx.y;
    int c  = blockIdx.z;
    int tid = threadIdx.x;
    int lane = tid & 31, wid = tid >> 5;
    int wm = wid >> 2, wn = wid & 3;
    int g  = lane >> 2;
    int t2 = (lane & 3) * 2;

    // stage A: nf fp32 -> fp16 (16 floats/thread)
    {
        int row = tid >> 2, sg = tid & 3;
        const float4* src = reinterpret_cast<const float4*>(
            nf + ((size_t)(c * N_ + n0 + row) * T_ + t) * INF_ + sg * 16);
        __half2* dst = reinterpret_cast<__half2*>(As + row * LDA2 + sg * 16);
        #pragma unroll
        for (int j = 0; j < 4; ++j) {
            float4 v = src[j];
            dst[j * 2]     = __floats2half2_rn(v.x, v.y);
            dst[j * 2 + 1] = __floats2half2_rn(v.z, v.w);
        }
    }
    // stage B: pure copy of pre-converted g_fch[t]
    {
        int row = tid >> 2, sg = tid & 3;
        const int4* src = reinterpret_cast<const int4*>(
            g_fch + ((size_t)t * INF_ + row) * K_ + sg * 64);
        int4* dst = reinterpret_cast<int4*>(Bs + row * LDB2 + sg * 64);
        #pragma unroll
        for (int j = 0; j < 8; ++j) dst[j] = src[j];
    }
    __syncthreads();

    float acc[2][8][4];
    #pragma unroll
    for (int mi = 0; mi < 2; ++mi)
        #pragma unroll
        for (int ni = 0; ni < 8; ++ni)
            #pragma unroll
            for (int q = 0; q < 4; ++q) acc[mi][ni][q] = 0.f;

    #pragma unroll
    for (int ki = 0; ki < 4; ++ki) {
        int k0 = ki * 16;
        uint32_t af[2][4];
        #pragma unroll
        for (int mi = 0; mi < 2; ++mi) {
            int row = wm * 32 + mi * 16 + (lane & 15);
            int col = k0 + ((lane >> 4) << 3);
            uint32_t addr = smem_u32(As + row * LDA2 + col);
            asm volatile("ldmatrix.sync.aligned.m8n8.x4.shared.b16 {%0,%1,%2,%3}, [%4];"
                         : "=r"(af[mi][0]), "=r"(af[mi][1]), "=r"(af[mi][2]), "=r"(af[mi][3])
                         : "r"(addr));
        }
        #pragma unroll
        for (int nj = 0; nj < 4; ++nj) {
            int krow = k0 + ((lane >> 3) & 1) * 8 + (lane & 7);
            int ncol = wn * 64 + nj * 16 + (lane >> 4) * 8;
            uint32_t addr = smem_u32(Bs + krow * LDB2 + ncol);
            uint32_t q0, q1, q2, q3;
            asm volatile("ldmatrix.sync.aligned.m8n8.x4.trans.shared.b16 {%0,%1,%2,%3}, [%4];"
                         : "=r"(q0), "=r"(q1), "=r"(q2), "=r"(q3) : "r"(addr));
            #pragma unroll
            for (int mi = 0; mi < 2; ++mi) {
                asm volatile(
                    "mma.sync.aligned.m16n8k16.row.col.f32.f16.f16.f32 "
                    "{%0,%1,%2,%3},{%4,%5,%6,%7},{%8,%9},{%0,%1,%2,%3};"
                    : "+f"(acc[mi][2*nj][0]), "+f"(acc[mi][2*nj][1]),
                      "+f"(acc[mi][2*nj][2]), "+f"(acc[mi][2*nj][3])
                    : "r"(af[mi][0]), "r"(af[mi][1]), "r"(af[mi][2]), "r"(af[mi][3]),
                      "r"(q0), "r"(q1));
                asm volatile(
                    "mma.sync.aligned.m16n8k16.row.col.f32.f16.f16.f32 "
                    "{%0,%1,%2,%3},{%4,%5,%6,%7},{%8,%9},{%0,%1,%2,%3};"
                    : "+f"(acc[mi][2*nj+1][0]), "+f"(acc[mi][2*nj+1][1]),
                      "+f"(acc[mi][2*nj+1][2]), "+f"(acc[mi][2*nj+1][3])
                    : "r"(af[mi][0]), "r"(af[mi][1]), "r"(af[mi][2]), "r"(af[mi][3]),
                      "r"(q2), "r"(q3));
            }
        }
    }

    // epilogue: scrambled masked fp16 stores
    #pragma unroll
    for (int mi = 0; mi < 2; ++mi) {
        #pragma unroll
        for (int rr = 0; rr < 2; ++rr) {
            int row = wm * 32 + mi * 16 + rr * 8 + g;
            int q = t * 1024 + n0 + row;
            int u = q / 3, b = q - u * 3;
            float md = g_mdst[c * N_ + u];
            __half* fd = g_Fd + b * 64;
            #pragma unroll
            for (int ni = 0; ni < 8; ++ni) {
                int cc = wn * 64 + ni * 8 + t2;
                int h = cc >> 6, f = cc & 63;
                float v0 = acc[mi][ni][rr * 2 + 0] * md;
                float v1 = acc[mi][ni][rr * 2 + 1] * md;
                *reinterpret_cast<__half2*>(
                    fd + ((size_t)(c * 4 + h) * N_ + u) * S_ + f) =
                    __floats2half2_rn(v0, v1);
            }
        }
    }
}

// ---------------- K4: softmax over c -> a (fp32) + At (fp16 transposed) ----------------
__global__ __launch_bounds__(256) void k_attn_a(float* __restrict__ a_out) {
    int v = blockIdx.y;
    int u = blockIdx.x * 256 + threadIdx.x;
    __shared__ float s_asrc[32];
    if (threadIdx.x < 32) {
        int c = threadIdx.x >> 2, h = threadIdx.x & 3;
        s_asrc[threadIdx.x] = g_asrc[(c * N_ + v) * H_ + h] * g_msrc[c * N_ + v];
    }
    __syncthreads();

    float e[8][4];
    float den[4] = {0.f, 0.f, 0.f, 0.f};
    #pragma unroll
    for (int c = 0; c < 8; ++c) {
        float md = g_mdst[c * N_ + u];
        float4 d = *reinterpret_cast<const float4*>(&g_adst[(c * N_ + u) * H_]);
        float zd[4] = {d.x * md, d.y * md, d.z * md, d.w * md};
        #pragma unroll
        for (int h = 0; h < 4; ++h) {
            float z = s_asrc[c * 4 + h] + zd[h];
            z = (z >= 0.f) ? z : 0.2f * z;
            z = clipf(z);
            float ee = fexp(z);
            e[c][h] = ee;
            den[h] += ee;
        }
    }
    float inv[4];
    #pragma unroll
    for (int h = 0; h < 4; ++h) inv[h] = 1.0f / den[h];

    #pragma unroll
    for (int c = 0; c < 8; ++c) {
        float a0 = e[c][0] * inv[0];
        float a1 = e[c][1] * inv[1];
        float a2 = e[c][2] * inv[2];
        float a3 = e[c][3] * inv[3];
        reinterpret_cast<float4*>(a_out)[(size_t)(c * N_ + v) * N_ + u] =
            make_float4(a0, a1, a2, a3);
        g_At[((size_t)(c * 4 + 0) * N_ + v) * N_ + u] = __float2half(a0);
        g_At[((size_t)(c * 4 + 1) * N_ + v) * N_ + u] = __float2half(a1);
        g_At[((size_t)(c * 4 + 2) * N_ + v) * N_ + u] = __float2half(a2);
        g_At[((size_t)(c * 4 + 3) * N_ + v) * N_ + u] = __float2half(a3);
    }
}

// ---------------- K5: per-block (c, 64-v-tile), loop h: acc 16 chunks, relu-fold; NO atomics ----------------
#define LDA 72
#define LDB 200
__global__ __launch_bounds__(256) void k_m(float* __restrict__ outs) {
    __shared__ __align__(16) __half a_s[64 * LDA];
    __shared__ __align__(16) __half b_s[64 * LDB];

    int c  = blockIdx.y;
    int v0 = blockIdx.x * 64;
    int tid = threadIdx.x;
    int lane = tid & 31, wid = tid >> 5;
    int wv = wid >> 2, wf = wid & 3;
    int g  = lane >> 2;
    int t2 = (lane & 3) * 2;

    const __half* At_c = g_At + (size_t)(c * 4) * N_ * N_;
    const __half* Fd_c = g_Fd + (size_t)(c * 4) * N_ * S_;

    float acc[2][6][4];
    float osum[2][6][4];
    #pragma unroll
    for (int mi = 0; mi < 2; ++mi)
        #pragma unroll
        for (int ni = 0; ni < 6; ++ni)
            #pragma unroll
            for (int q = 0; q < 4; ++q) { acc[mi][ni][q] = 0.f; osum[mi][ni][q] = 0.f; }

    int r = tid >> 2, seg = tid & 3;

    // prefetch chunk 0 (h=0, u0=0)
    int4 av0, av1, bv[6];
    {
        const int4* ap = reinterpret_cast<const int4*>(At_c + (size_t)(v0 + r) * N_ + seg * 16);
        av0 = ap[0]; av1 = ap[1];
        const int4* bp = reinterpret_cast<const int4*>(Fd_c + (size_t)r * S_ + seg * 48);
        #pragma unroll
        for (int j = 0; j < 6; ++j) bv[j] = bp[j];
    }

    for (int kk = 0; kk < 64; ++kk) {
        int4* ad = reinterpret_cast<int4*>(a_s + r * LDA + seg * 16);
        ad[0] = av0; ad[1] = av1;
        int4* bd = reinterpret_cast<int4*>(b_s + r * LDB + seg * 48);
        #pragma unroll
        for (int j = 0; j < 6; ++j) bd[j] = bv[j];
        __syncthreads();

        if (kk < 63) {
            int kn = kk + 1;
            int hn = kn >> 4, u0 = (kn & 15) << 6;
            const int4* ap = reinterpret_cast<const int4*>(
                At_c + (size_t)hn * N_ * N_ + (size_t)(v0 + r) * N_ + u0 + seg * 16);
            av0 = ap[0]; av1 = ap[1];
            const int4* bp = reinterpret_cast<const int4*>(
                Fd_c + (size_t)hn * N_ * S_ + (size_t)(u0 + r) * S_ + seg * 48);
            #pragma unroll
            for (int j = 0; j < 6; ++j) bv[j] = bp[j];
        }

        #pragma unroll
        for (int ki = 0; ki < 4; ++ki) {
            int k0 = ki * 16;
            uint32_t af[2][4];
            #pragma unroll
            for (int mi = 0; mi < 2; ++mi) {
                int row = wv * 32 + mi * 16 + (lane & 15);
                int col = k0 + ((lane >> 4) << 3);
                uint32_t addr = smem_u32(a_s + row * LDA + col);
                asm volatile("ldmatrix.sync.aligned.m8n8.x4.shared.b16 {%0,%1,%2,%3}, [%4];"
                             : "=r"(af[mi][0]), "=r"(af[mi][1]), "=r"(af[mi][2]), "=r"(af[mi][3])
                             : "r"(addr));
            }
            #pragma unroll
            for (int nj = 0; nj < 3; ++nj) {
                int krow = k0 + ((lane >> 3) & 1) * 8 + (lane & 7);
                int ncol = wf * 48 + nj * 16 + (lane >> 4) * 8;
                uint32_t addr = smem_u32(b_s + krow * LDB + ncol);
                uint32_t q0, q1, q2, q3;
                asm volatile("ldmatrix.sync.aligned.m8n8.x4.trans.shared.b16 {%0,%1,%2,%3}, [%4];"
                             : "=r"(q0), "=r"(q1), "=r"(q2), "=r"(q3) : "r"(addr));
                #pragma unroll
                for (int mi = 0; mi < 2; ++mi) {
                    asm volatile(
                        "mma.sync.aligned.m16n8k16.row.col.f32.f16.f16.f32 "
                        "{%0,%1,%2,%3},{%4,%5,%6,%7},{%8,%9},{%0,%1,%2,%3};"
                        : "+f"(acc[mi][2*nj][0]), "+f"(acc[mi][2*nj][1]),
                          "+f"(acc[mi][2*nj][2]), "+f"(acc[mi][2*nj][3])
                        : "r"(af[mi][0]), "r"(af[mi][1]), "r"(af[mi][2]), "r"(af[mi][3]),
                          "r"(q0), "r"(q1));
                    asm volatile(
                        "mma.sync.aligned.m16n8k16.row.col.f32.f16.f16.f32 "
                        "{%0,%1,%2,%3},{%4,%5,%6,%7},{%8,%9},{%0,%1,%2,%3};"
                        : "+f"(acc[mi][2*nj+1][0]), "+f"(acc[mi][2*nj+1][1]),
                          "+f"(acc[mi][2*nj+1][2]), "+f"(acc[mi][2*nj+1][3])
                        : "r"(af[mi][0]), "r"(af[mi][1]), "r"(af[mi][2]), "r"(af[mi][3]),
                          "r"(q2), "r"(q3));
                }
            }
        }

        // end of one h's 16 chunks: relu-fold acc into osum, reset acc
        if ((kk & 15) == 15) {
            #pragma unroll
            for (int mi = 0; mi < 2; ++mi)
                #pragma unroll
                for (int ni = 0; ni < 6; ++ni)
                    #pragma unroll
                    for (int q = 0; q < 4; ++q) {
                        osum[mi][ni][q] += fmaxf(acc[mi][ni][q], 0.f);
                        acc[mi][ni][q] = 0.f;
                    }
        }
        __syncthreads();
    }

    // epilogue: plain coalesced stores (each element written exactly once)
    #pragma unroll
    for (int mi = 0; mi < 2; ++mi) {
        #pragma unroll
        for (int ni = 0; ni < 6; ++ni) {
            int v = v0 + wv * 32 + mi * 16 + g;
            int f = wf * 48 + ni * 8 + t2;
            float* o0 = outs + (size_t)(c * N_ + v) * S_ + f;
            o0[0] = osum[mi][ni][0];
            o0[1] = osum[mi][ni][1];
            float* o1 = outs + (size_t)(c * N_ + v + 8) * S_ + f;
            o1[0] = osum[mi][ni][2];
            o1[1] = osum[mi][ni][3];
        }
    }
}

// ---------------- launch ----------------
extern "C" void kernel_launch(void* const* d_in, const int* in_sizes, int n_in,
                              void* d_out, int out_size) {
    const int*   edge = (const int*)d_in[0];
    const float* nf   = (const float*)d_in[1];
    const float* fc   = (const float*)d_in[2];
    const float* asv  = (const float*)d_in[3];
    const float* adv  = (const float*)d_in[4];

    float* outs  = (float*)d_out;                          // (8,1024,3,64)
    float* a_out = outs + (size_t)C_ * N_ * T_ * F_;       // (8,1024,1024,4)

    k_prep<<<233, 256>>>(fc, asv, adv);
    k_scatter<<<E_ / 256, 256>>>(edge);
    k_av<<<1024, 256>>>(nf);
    k_feat_tc<<<dim3(16, 3, 8), 256>>>(nf);     // 4th launch -> ncu capture slot
    k_attn_a<<<dim3(4, N_), 256>>>(a_out);
    k_m<<<dim3(16, 8), 256>>>(outs);
}

// round 14
// speedup vs baseline: 1.1607x; 1.1607x over previous
#include <cuda_runtime.h>
#include <cuda_fp16.h>
#include <cstdint>

#define C_   8
#define N_   1024
#define T_   3
#define INF_ 64
#define H_   4
#define F_   64
#define K_   256      // H*F
#define S_   192      // T*F
#define E_   65536
#define CN_  8192

// ---------------- scratch ----------------
__device__ __align__(16) float  g_msrc[CN_];
__device__ __align__(16) float  g_mdst[CN_];
__device__ __align__(16) float  g_asrc[C_*N_*H_];
__device__ __align__(16) float  g_adst[C_*N_*H_];
__device__ __align__(16) float  g_wsrc[T_*3*H_*64];        // [t][b][h][i]
__device__ __align__(16) float  g_wdst[T_*3*H_*64];
__device__ __align__(16) __half g_fch[T_*INF_*K_];         // fc in fp16
__device__ __align__(16) __half g_Fd[(size_t)C_*H_*N_*S_]; // [c*4+h][u][s]
__device__ __align__(16) __half g_At[(size_t)C_*H_*N_*N_]; // [c*4+h][v][u]

// ---------------- helpers ----------------
__device__ __forceinline__ float clipf(float x) {
    return fminf(fmaxf(x, -1e9f), 1e9f);
}
__device__ __forceinline__ float fexp(float x) {
    float y  = x * 1.4426950408889634f;
    int   ni = __float2int_rn(y);
    float f  = y - (float)ni;
    float p  = 1.5403530393381608e-4f;
    p = fmaf(p, f, 1.3333558146428443e-3f);
    p = fmaf(p, f, 9.6181291076284770e-3f);
    p = fmaf(p, f, 5.5504108664821580e-2f);
    p = fmaf(p, f, 2.4022650695910071e-1f);
    p = fmaf(p, f, 6.9314718055994531e-1f);
    p = fmaf(p, f, 1.0f);
    return __int_as_float((ni + 127) << 23) * p;
}
__device__ __forceinline__ uint32_t smem_u32(const void* p) {
    return (uint32_t)__cvta_generic_to_shared(p);
}

// ---------------- K_prep: zero outs + zero masks + fc->fp16 + compute w ----------------
__global__ __launch_bounds__(256) void k_prep(float* __restrict__ outs,
                                              const float* __restrict__ fc,
                                              const float* __restrict__ asv,
                                              const float* __restrict__ adv) {
    int blk = blockIdx.x;
    int tid = threadIdx.x;
    if (blk < 1536) {
        reinterpret_cast<float4*>(outs)[blk * 256 + tid] = make_float4(0.f, 0.f, 0.f, 0.f);
        return;
    }
    if (blk < 1568) {
        int i = (blk - 1536) * 256 + tid;
        g_msrc[i] = 0.f; g_mdst[i] = 0.f;
        return;
    }
    if (blk < 1760) {                       // fc fp32 -> fp16 (49152 elements)
        int i = (blk - 1568) * 256 + tid;
        g_fch[i] = __float2half(fc[i]);
        return;
    }
    int w = blk - 1760;                     // 9 blocks: w[t][b]
    int t = w / 3, b = w - t * 3;
    __shared__ float s_a[256], s_d[256];
    {
        int hh = tid >> 6, ff = tid & 63;
        s_a[tid] = asv[hh * S_ + b * 64 + ff];
        s_d[tid] = adv[hh * S_ + b * 64 + ff];
    }
    __syncthreads();
    int h = tid >> 6, i = tid & 63;
    const float4* fp = reinterpret_cast<const float4*>(
        fc + ((size_t)t * INF_ + i) * K_ + h * 64);
    float4 v[16];
    #pragma unroll
    for (int j = 0; j < 16; ++j) v[j] = fp[j];
    float ws = 0.f, wd = 0.f;
    #pragma unroll
    for (int j = 0; j < 16; ++j) {
        const float* sa = s_a + h * 64 + j * 4;
        const float* sd = s_d + h * 64 + j * 4;
        ws = fmaf(v[j].x, sa[0], ws); wd = fmaf(v[j].x, sd[0], wd);
        ws = fmaf(v[j].y, sa[1], ws); wd = fmaf(v[j].y, sd[1], wd);
        ws = fmaf(v[j].z, sa[2], ws); wd = fmaf(v[j].z, sd[2], wd);
        ws = fmaf(v[j].w, sa[3], ws); wd = fmaf(v[j].w, sd[3], wd);
    }
    int o = ((t * 3 + b) * 4 + h) * 64 + i;
    g_wsrc[o] = ws;
    g_wdst[o] = wd;
}

// ---------------- K1: scatter edge masks (int32) ----------------
__global__ __launch_bounds__(256) void k_scatter(const int* __restrict__ edge) {
    int i = blockIdx.x * 256 + threadIdx.x;
    if (i < E_) {
        g_msrc[edge[i]      & (CN_ - 1)] = 1.f;
        g_mdst[edge[E_ + i] & (CN_ - 1)] = 1.f;
    }
}

// ---------------- Kav: a_src/a_dst (exact fp32) ----------------
__global__ __launch_bounds__(256) void k_av(const float* __restrict__ nf) {
    int W    = blockIdx.x * 8 + (threadIdx.x >> 5);
    int lane = threadIdx.x & 31;
    int c = W >> 10, u = W & 1023;

    float as[4] = {0.f, 0.f, 0.f, 0.f};
    float ad[4] = {0.f, 0.f, 0.f, 0.f};
    #pragma unroll
    for (int b = 0; b < 3; ++b) {
        int q = 3 * u + b, t = q >> 10, n = q & 1023;
        const float* row = nf + ((size_t)(c * N_ + n) * T_ + t) * INF_;
        float x0 = row[lane], x1 = row[lane + 32];
        const float* ws = g_wsrc + ((t * 3 + b) * 4) * 64;
        const float* wd = g_wdst + ((t * 3 + b) * 4) * 64;
        #pragma unroll
        for (int h = 0; h < 4; ++h) {
            as[h] = fmaf(x0, ws[h * 64 + lane], as[h]);
            as[h] = fmaf(x1, ws[h * 64 + lane + 32], as[h]);
            ad[h] = fmaf(x0, wd[h * 64 + lane], ad[h]);
            ad[h] = fmaf(x1, wd[h * 64 + lane + 32], ad[h]);
        }
    }
    #pragma unroll
    for (int o = 16; o; o >>= 1) {
        #pragma unroll
        for (int h = 0; h < 4; ++h) {
            as[h] += __shfl_xor_sync(0xffffffffu, as[h], o);
            ad[h] += __shfl_xor_sync(0xffffffffu, ad[h], o);
        }
    }
    if (lane == 0) {
        int base = (c * N_ + u) * H_;
        *reinterpret_cast<float4*>(&g_asrc[base]) = make_float4(as[0], as[1], as[2], as[3]);
        *reinterpret_cast<float4*>(&g_adst[base]) = make_float4(ad[0], ad[1], ad[2], ad[3]);
    }
}

// ---------------- K2: feat GEMM tensor cores, M=64 tiles, B from g_fch ----------------
#define LDA2 72
#define LDB2 264
__global__ __launch_bounds__(256) void k_feat_tc(const float* __restrict__ nf) {
    __shared__ __align__(16) __half As[64 * LDA2];
    __shared__ __align__(16) __half Bs[64 * LDB2];

    int n0 = blockIdx.x * 64;
    int t  = blockIdx.y;
    int c  = blockIdx.z;
    int tid = threadIdx.x;
    int lane = tid & 31, wid = tid >> 5;
    int wm = wid >> 2, wn = wid & 3;
    int g  = lane >> 2;
    int t2 = (lane & 3) * 2;

    // stage A: nf fp32 -> fp16 (16 floats/thread)
    {
        int row = tid >> 2, sg = tid & 3;
        const float4* src = reinterpret_cast<const float4*>(
            nf + ((size_t)(c * N_ + n0 + row) * T_ + t) * INF_ + sg * 16);
        __half2* dst = reinterpret_cast<__half2*>(As + row * LDA2 + sg * 16);
        #pragma unroll
        for (int j = 0; j < 4; ++j) {
            float4 v = src[j];
            dst[j * 2]     = __floats2half2_rn(v.x, v.y);
            dst[j * 2 + 1] = __floats2half2_rn(v.z, v.w);
        }
    }
    // stage B: pure copy of pre-converted g_fch[t]
    {
        int row = tid >> 2, sg = tid & 3;
        const int4* src = reinterpret_cast<const int4*>(
            g_fch + ((size_t)t * INF_ + row) * K_ + sg * 64);
        int4* dst = reinterpret_cast<int4*>(Bs + row * LDB2 + sg * 64);
        #pragma unroll
        for (int j = 0; j < 8; ++j) dst[j] = src[j];
    }
    __syncthreads();

    float acc[2][8][4];
    #pragma unroll
    for (int mi = 0; mi < 2; ++mi)
        #pragma unroll
        for (int ni = 0; ni < 8; ++ni)
            #pragma unroll
            for (int q = 0; q < 4; ++q) acc[mi][ni][q] = 0.f;

    #pragma unroll
    for (int ki = 0; ki < 4; ++ki) {
        int k0 = ki * 16;
        uint32_t af[2][4];
        #pragma unroll
        for (int mi = 0; mi < 2; ++mi) {
            int row = wm * 32 + mi * 16 + (lane & 15);
            int col = k0 + ((lane >> 4) << 3);
            uint32_t addr = smem_u32(As + row * LDA2 + col);
            asm volatile("ldmatrix.sync.aligned.m8n8.x4.shared.b16 {%0,%1,%2,%3}, [%4];"
                         : "=r"(af[mi][0]), "=r"(af[mi][1]), "=r"(af[mi][2]), "=r"(af[mi][3])
                         : "r"(addr));
        }
        #pragma unroll
        for (int nj = 0; nj < 4; ++nj) {
            int krow = k0 + ((lane >> 3) & 1) * 8 + (lane & 7);
            int ncol = wn * 64 + nj * 16 + (lane >> 4) * 8;
            uint32_t addr = smem_u32(Bs + krow * LDB2 + ncol);
            uint32_t q0, q1, q2, q3;
            asm volatile("ldmatrix.sync.aligned.m8n8.x4.trans.shared.b16 {%0,%1,%2,%3}, [%4];"
                         : "=r"(q0), "=r"(q1), "=r"(q2), "=r"(q3) : "r"(addr));
            #pragma unroll
            for (int mi = 0; mi < 2; ++mi) {
                asm volatile(
                    "mma.sync.aligned.m16n8k16.row.col.f32.f16.f16.f32 "
                    "{%0,%1,%2,%3},{%4,%5,%6,%7},{%8,%9},{%0,%1,%2,%3};"
                    : "+f"(acc[mi][2*nj][0]), "+f"(acc[mi][2*nj][1]),
                      "+f"(acc[mi][2*nj][2]), "+f"(acc[mi][2*nj][3])
                    : "r"(af[mi][0]), "r"(af[mi][1]), "r"(af[mi][2]), "r"(af[mi][3]),
                      "r"(q0), "r"(q1));
                asm volatile(
                    "mma.sync.aligned.m16n8k16.row.col.f32.f16.f16.f32 "
                    "{%0,%1,%2,%3},{%4,%5,%6,%7},{%8,%9},{%0,%1,%2,%3};"
                    : "+f"(acc[mi][2*nj+1][0]), "+f"(acc[mi][2*nj+1][1]),
                      "+f"(acc[mi][2*nj+1][2]), "+f"(acc[mi][2*nj+1][3])
                    : "r"(af[mi][0]), "r"(af[mi][1]), "r"(af[mi][2]), "r"(af[mi][3]),
                      "r"(q2), "r"(q3));
            }
        }
    }

    // epilogue: scrambled masked fp16 stores
    #pragma unroll
    for (int mi = 0; mi < 2; ++mi) {
        #pragma unroll
        for (int rr = 0; rr < 2; ++rr) {
            int row = wm * 32 + mi * 16 + rr * 8 + g;
            int q = t * 1024 + n0 + row;
            int u = q / 3, b = q - u * 3;
            float md = g_mdst[c * N_ + u];
            __half* fd = g_Fd + b * 64;
            #pragma unroll
            for (int ni = 0; ni < 8; ++ni) {
                int cc = wn * 64 + ni * 8 + t2;
                int h = cc >> 6, f = cc & 63;
                float v0 = acc[mi][ni][rr * 2 + 0] * md;
                float v1 = acc[mi][ni][rr * 2 + 1] * md;
                *reinterpret_cast<__half2*>(
                    fd + ((size_t)(c * 4 + h) * N_ + u) * S_ + f) =
                    __floats2half2_rn(v0, v1);
            }
        }
    }
}

// ---------------- K4: softmax over c -> a (fp32) + At (fp16 transposed) ----------------
__global__ __launch_bounds__(256) void k_attn_a(float* __restrict__ a_out) {
    int v = blockIdx.y;
    int u = blockIdx.x * 256 + threadIdx.x;
    __shared__ float s_asrc[32];
    if (threadIdx.x < 32) {
        int c = threadIdx.x >> 2, h = threadIdx.x & 3;
        s_asrc[threadIdx.x] = g_asrc[(c * N_ + v) * H_ + h] * g_msrc[c * N_ + v];
    }
    __syncthreads();

    float e[8][4];
    float den[4] = {0.f, 0.f, 0.f, 0.f};
    #pragma unroll
    for (int c = 0; c < 8; ++c) {
        float md = g_mdst[c * N_ + u];
        float4 d = *reinterpret_cast<const float4*>(&g_adst[(c * N_ + u) * H_]);
        float zd[4] = {d.x * md, d.y * md, d.z * md, d.w * md};
        #pragma unroll
        for (int h = 0; h < 4; ++h) {
            float z = s_asrc[c * 4 + h] + zd[h];
            z = (z >= 0.f) ? z : 0.2f * z;
            z = clipf(z);
            float ee = fexp(z);
            e[c][h] = ee;
            den[h] += ee;
        }
    }
    float inv[4];
    #pragma unroll
    for (int h = 0; h < 4; ++h) inv[h] = 1.0f / den[h];

    #pragma unroll
    for (int c = 0; c < 8; ++c) {
        float a0 = e[c][0] * inv[0];
        float a1 = e[c][1] * inv[1];
        float a2 = e[c][2] * inv[2];
        float a3 = e[c][3] * inv[3];
        reinterpret_cast<float4*>(a_out)[(size_t)(c * N_ + v) * N_ + u] =
            make_float4(a0, a1, a2, a3);
        g_At[((size_t)(c * 4 + 0) * N_ + v) * N_ + u] = __float2half(a0);
        g_At[((size_t)(c * 4 + 1) * N_ + v) * N_ + u] = __float2half(a1);
        g_At[((size_t)(c * 4 + 2) * N_ + v) * N_ + u] = __float2half(a2);
        g_At[((size_t)(c * 4 + 3) * N_ + v) * N_ + u] = __float2half(a3);
    }
}

// ---------------- K5: m = A @ Fd; 128-row tiles, reg prefetch, x4-trans ldmatrix (R10 proven) ----------------
#define LDA 72
#define LDB 200
__global__ __launch_bounds__(256) void k_m(float* __restrict__ outs) {
    __shared__ __align__(16) __half a_s[128 * LDA];
    __shared__ __align__(16) __half b_s[64 * LDB];

    int ch = blockIdx.y;
    int c  = ch >> 2;
    int v0 = blockIdx.x * 128;
    int tid = threadIdx.x;
    int lane = tid & 31, wid = tid >> 5;
    int wv = wid >> 2, wf = wid & 3;
    int g  = lane >> 2;
    int t2 = (lane & 3) * 2;

    const __half* Ag = g_At + (size_t)ch * N_ * N_ + (size_t)v0 * N_;
    const __half* Bg = g_Fd + (size_t)ch * N_ * S_;

    float acc[4][6][4];
    #pragma unroll
    for (int mi = 0; mi < 4; ++mi)
        #pragma unroll
        for (int ni = 0; ni < 6; ++ni)
            #pragma unroll
            for (int q = 0; q < 4; ++q) acc[mi][ni][q] = 0.f;

    int r2 = tid >> 1, sg2 = tid & 1;
    int r4 = tid >> 2, sg4 = tid & 3;

    int4 av[4];
    {
        const int4* ap = reinterpret_cast<const int4*>(Ag + (size_t)r2 * N_ + sg2 * 32);
        #pragma unroll
        for (int j = 0; j < 4; ++j) av[j] = ap[j];
    }
    int4 bv[6];
    {
        const int4* bp = reinterpret_cast<const int4*>(Bg + (size_t)r4 * S_ + sg4 * 48);
        #pragma unroll
        for (int j = 0; j < 6; ++j) bv[j] = bp[j];
    }

    for (int u0 = 0; u0 < N_; u0 += 64) {
        int4* ad = reinterpret_cast<int4*>(a_s + r2 * LDA + sg2 * 32);
        #pragma unroll
        for (int j = 0; j < 4; ++j) ad[j] = av[j];
        int4* bd = reinterpret_cast<int4*>(b_s + r4 * LDB + sg4 * 48);
        #pragma unroll
        for (int j = 0; j < 6; ++j) bd[j] = bv[j];
        __syncthreads();

        if (u0 + 64 < N_) {
            const int4* ap = reinterpret_cast<const int4*>(Ag + (size_t)r2 * N_ + u0 + 64 + sg2 * 32);
            #pragma unroll
            for (int j = 0; j < 4; ++j) av[j] = ap[j];
            const int4* bp = reinterpret_cast<const int4*>(Bg + (size_t)(u0 + 64 + r4) * S_ + sg4 * 48);
            #pragma unroll
            for (int j = 0; j < 6; ++j) bv[j] = bp[j];
        }

        #pragma unroll
        for (int ki = 0; ki < 4; ++ki) {
            int k0 = ki * 16;
            uint32_t af[4][4];
            #pragma unroll
            for (int mi = 0; mi < 4; ++mi) {
                int row = wv * 64 + mi * 16 + (lane & 15);
                int col = k0 + ((lane >> 4) << 3);
                uint32_t addr = smem_u32(a_s + row * LDA + col);
                asm volatile("ldmatrix.sync.aligned.m8n8.x4.shared.b16 {%0,%1,%2,%3}, [%4];"
                             : "=r"(af[mi][0]), "=r"(af[mi][1]), "=r"(af[mi][2]), "=r"(af[mi][3])
                             : "r"(addr));
            }
            #pragma unroll
            for (int nj = 0; nj < 3; ++nj) {
                int krow = k0 + ((lane >> 3) & 1) * 8 + (lane & 7);
                int ncol = wf * 48 + nj * 16 + (lane >> 4) * 8;
                uint32_t addr = smem_u32(b_s + krow * LDB + ncol);
                uint32_t q0, q1, q2, q3;
                asm volatile("ldmatrix.sync.aligned.m8n8.x4.trans.shared.b16 {%0,%1,%2,%3}, [%4];"
                             : "=r"(q0), "=r"(q1), "=r"(q2), "=r"(q3) : "r"(addr));
                #pragma unroll
                for (int mi = 0; mi < 4; ++mi) {
                    asm volatile(
                        "mma.sync.aligned.m16n8k16.row.col.f32.f16.f16.f32 "
                        "{%0,%1,%2,%3},{%4,%5,%6,%7},{%8,%9},{%0,%1,%2,%3};"
                        : "+f"(acc[mi][2*nj][0]), "+f"(acc[mi][2*nj][1]),
                          "+f"(acc[mi][2*nj][2]), "+f"(acc[mi][2*nj][3])
                        : "r"(af[mi][0]), "r"(af[mi][1]), "r"(af[mi][2]), "r"(af[mi][3]),
                          "r"(q0), "r"(q1));
                    asm volatile(
                        "mma.sync.aligned.m16n8k16.row.col.f32.f16.f16.f32 "
                        "{%0,%1,%2,%3},{%4,%5,%6,%7},{%8,%9},{%0,%1,%2,%3};"
                        : "+f"(acc[mi][2*nj+1][0]), "+f"(acc[mi][2*nj+1][1]),
                          "+f"(acc[mi][2*nj+1][2]), "+f"(acc[mi][2*nj+1][3])
                        : "r"(af[mi][0]), "r"(af[mi][1]), "r"(af[mi][2]), "r"(af[mi][3]),
                          "r"(q2), "r"(q3));
                }
            }
        }
        __syncthreads();
    }

    #pragma unroll
    for (int mi = 0; mi < 4; ++mi) {
        #pragma unroll
        for (int ni = 0; ni < 6; ++ni) {
            int v = v0 + wv * 64 + mi * 16 + g;
            int f = wf * 48 + ni * 8 + t2;
            float* o0 = outs + (size_t)(c * N_ + v) * S_ + f;
            atomicAdd(o0,     fmaxf(acc[mi][ni][0], 0.f));
            atomicAdd(o0 + 1, fmaxf(acc[mi][ni][1], 0.f));
            float* o1 = outs + (size_t)(c * N_ + v + 8) * S_ + f;
            atomicAdd(o1,     fmaxf(acc[mi][ni][2], 0.f));
            atomicAdd(o1 + 1, fmaxf(acc[mi][ni][3], 0.f));
        }
    }
}

// ---------------- launch ----------------
extern "C" void kernel_launch(void* const* d_in, const int* in_sizes, int n_in,
                              void* d_out, int out_size) {
    const int*   edge = (const int*)d_in[0];
    const float* nf   = (const float*)d_in[1];
    const float* fc   = (const float*)d_in[2];
    const float* asv  = (const float*)d_in[3];
    const float* adv  = (const float*)d_in[4];

    float* outs  = (float*)d_out;                          // (8,1024,3,64)
    float* a_out = outs + (size_t)C_ * N_ * T_ * F_;       // (8,1024,1024,4)

    k_prep<<<1769, 256>>>(outs, fc, asv, adv);
    k_scatter<<<E_ / 256, 256>>>(edge);
    k_av<<<1024, 256>>>(nf);
    k_feat_tc<<<dim3(16, 3, 8), 256>>>(nf);
    k_attn_a<<<dim3(4, N_), 256>>>(a_out);
    k_m<<<dim3(8, 32), 256>>>(outs);
}